// round 3
// baseline (speedup 1.0000x reference)
#include <cuda_runtime.h>
#include <math.h>

#define T_SEQ 8192
#define HDIM  1024
#define NBLK  128     // scan CTAs (<=148 SMs -> all co-resident)

// ---------------- static device scratch (no runtime allocation) ----------------
__device__ float           g_XP[3][T_SEQ * HDIM];   // xu, xr, xc projections
__device__ __align__(16) float g_hbuf[2][HDIM];     // double-buffered hidden state
__device__ unsigned        g_cnt;                   // global barrier counter

// ---------------- per-launch reset (graph-replay safe) ----------------
__global__ void reset_kernel() {
    int i = threadIdx.x;
    if (i == 0) g_cnt = 0u;
    for (int k = i; k < HDIM; k += 256) {
        g_hbuf[0][k] = 0.f;
        g_hbuf[1][k] = 0.f;
    }
}

// ---------------- Phase 1: C[z] = x @ U[z]^T + bias[z]  (fp32, NT) ----------------
// BM=128, BN=64, BK=16, 256 threads, per-thread 8x4 microtile.
__global__ __launch_bounds__(256) void proj_gemm(
    const float* __restrict__ x,
    const float* __restrict__ Uu, const float* __restrict__ Ur, const float* __restrict__ Uc,
    const float* __restrict__ Bu, const float* __restrict__ Br, const float* __restrict__ Bc)
{
    const int z = blockIdx.z;
    const float* __restrict__ Bmat = (z == 0) ? Uu : ((z == 1) ? Ur : Uc);
    const float* __restrict__ bias = (z == 0) ? Bu : ((z == 1) ? Br : Bc);
    float* __restrict__ C = g_XP[z];

    const int m0 = blockIdx.x * 128;
    const int n0 = blockIdx.y * 64;

    __shared__ __align__(16) float As[16][132];   // [k][m], padded
    __shared__ __align__(16) float Bs[16][68];    // [k][n], padded

    const int tid = threadIdx.x;
    const int tx  = tid & 15;   // n dir: cols tx*4 .. tx*4+3
    const int ty  = tid >> 4;   // m dir: rows ty*8 .. ty*8+7

    float acc[8][4];
#pragma unroll
    for (int i = 0; i < 8; i++)
#pragma unroll
        for (int j = 0; j < 4; j++) acc[i][j] = 0.f;

    for (int k0 = 0; k0 < HDIM; k0 += 16) {
        // Load A tile 128x16 (512 float4, 2 per thread), transposed into As[k][m]
#pragma unroll
        for (int i = 0; i < 2; i++) {
            int idx = tid * 2 + i;          // 0..511
            int row = idx >> 2;             // 0..127
            int c4  = idx & 3;              // which float4 in the 16-wide k-slab
            float4 v = *reinterpret_cast<const float4*>(x + (size_t)(m0 + row) * HDIM + k0 + c4 * 4);
            As[c4 * 4 + 0][row] = v.x;
            As[c4 * 4 + 1][row] = v.y;
            As[c4 * 4 + 2][row] = v.z;
            As[c4 * 4 + 3][row] = v.w;
        }
        // Load B tile 64x16 (256 float4, 1 per thread), transposed into Bs[k][n]
        {
            int row = tid >> 2;             // 0..63
            int c4  = tid & 3;
            float4 v = *reinterpret_cast<const float4*>(Bmat + (size_t)(n0 + row) * HDIM + k0 + c4 * 4);
            Bs[c4 * 4 + 0][row] = v.x;
            Bs[c4 * 4 + 1][row] = v.y;
            Bs[c4 * 4 + 2][row] = v.z;
            Bs[c4 * 4 + 3][row] = v.w;
        }
        __syncthreads();

#pragma unroll
        for (int k = 0; k < 16; k++) {
            float a[8], b[4];
#pragma unroll
            for (int i = 0; i < 8; i++) a[i] = As[k][ty * 8 + i];
#pragma unroll
            for (int j = 0; j < 4; j++) b[j] = Bs[k][tx * 4 + j];
#pragma unroll
            for (int i = 0; i < 8; i++)
#pragma unroll
                for (int j = 0; j < 4; j++) acc[i][j] = fmaf(a[i], b[j], acc[i][j]);
        }
        __syncthreads();
    }

    // Epilogue: add bias, store
    float4 bv = *reinterpret_cast<const float4*>(bias + n0 + tx * 4);
#pragma unroll
    for (int i = 0; i < 8; i++) {
        float4 o;
        o.x = acc[i][0] + bv.x;
        o.y = acc[i][1] + bv.y;
        o.z = acc[i][2] + bv.z;
        o.w = acc[i][3] + bv.w;
        *reinterpret_cast<float4*>(C + (size_t)(m0 + ty * 8 + i) * HDIM + n0 + tx * 4) = o;
    }
}

// ---------------- Phase 2: persistent sequential scan ----------------
__device__ __forceinline__ float sigmoidf_(float v) {
    return 1.f / (1.f + __expf(-v));
}

__global__ __launch_bounds__(256, 1) void scan_kernel(
    const float* __restrict__ Wu, const float* __restrict__ Wr, const float* __restrict__ Wc,
    float* __restrict__ out)   // out[0:1024] = h_final, out[1024 + t*1024 + r] = outputs
{
    __shared__ __align__(16) float hs[HDIM];

    const int tid = threadIdx.x;
    const int l   = tid & 31;
    const int w   = tid >> 5;
    const int r   = blockIdx.x * 8 + w;      // this warp's hidden row, 0..1023

    // Load the three weight rows into registers: lane l owns columns k*32 + l.
    float wu[32], wr[32], wc[32];
#pragma unroll
    for (int k = 0; k < 32; k++) {
        int c = k * 32 + l;
        wu[k] = __ldg(Wu + (size_t)r * HDIM + c);
        wr[k] = __ldg(Wr + (size_t)r * HDIM + c);
        wc[k] = __ldg(Wc + (size_t)r * HDIM + c);
    }

    const float* __restrict__ XPu = g_XP[0];
    const float* __restrict__ XPr = g_XP[1];
    const float* __restrict__ XPc = g_XP[2];

    unsigned target = 0;

#pragma unroll 1
    for (int t = 0; t < T_SEQ; ++t) {
        const float* hin  = g_hbuf[t & 1];
        float*       hout = g_hbuf[(t + 1) & 1];

        // Stage h_t into shared memory (coalesced, L1-bypassing)
        float4 hv4 = __ldcg(reinterpret_cast<const float4*>(hin) + tid);
        reinterpret_cast<float4*>(hs)[tid] = hv4;

        // Projections for this warp's row (only lane 0 needs them)
        float au = 0.f, ar = 0.f, ac = 0.f;
        if (l == 0) {
            size_t off = (size_t)t * HDIM + r;
            au = __ldcg(XPu + off);
            ar = __ldcg(XPr + off);
            ac = __ldcg(XPc + off);
        }
        __syncthreads();

        // Three dot products with the staged h
        float su = 0.f, sr = 0.f, sc = 0.f;
#pragma unroll
        for (int k = 0; k < 32; k++) {
            float hv = hs[k * 32 + l];
            su = fmaf(wu[k], hv, su);
            sr = fmaf(wr[k], hv, sr);
            sc = fmaf(wc[k], hv, sc);
        }
#pragma unroll
        for (int off = 16; off > 0; off >>= 1) {
            su += __shfl_down_sync(0xffffffffu, su, off);
            sr += __shfl_down_sync(0xffffffffu, sr, off);
            sc += __shfl_down_sync(0xffffffffu, sc, off);
        }

        if (l == 0) {
            float hprev = hs[r];
            float u  = sigmoidf_(au + su);
            float rg = sigmoidf_(ar + sr);
            float cd = sigmoidf_(ac + rg * sc);
            float hn = fmaf(u, hprev - cd, cd);   // u*h + (1-u)*cand
            __stcg(hout + r, hn);
            out[HDIM + (size_t)t * HDIM + r] = hn;
            if (t == T_SEQ - 1) out[r] = hn;
        }

        // Grid-wide barrier (monotonic counter; reset per launch)
        __syncthreads();
        if (tid == 0) {
            __threadfence();
            atomicAdd(&g_cnt, 1u);
            target += NBLK;
            while (*((volatile unsigned*)&g_cnt) < target) { }
            __threadfence();
        }
        __syncthreads();
    }
}

// ---------------- launch ----------------
extern "C" void kernel_launch(void* const* d_in, const int* in_sizes, int n_in,
                              void* d_out, int out_size) {
    const float* x  = (const float*)d_in[0];
    const float* Uu = (const float*)d_in[1];
    const float* Wu = (const float*)d_in[2];
    const float* Bu = (const float*)d_in[3];
    const float* Ur = (const float*)d_in[4];
    const float* Wr = (const float*)d_in[5];
    const float* Br = (const float*)d_in[6];
    const float* Uc = (const float*)d_in[7];
    const float* Wc = (const float*)d_in[8];
    const float* Bc = (const float*)d_in[9];
    float* out = (float*)d_out;

    reset_kernel<<<1, 256>>>();

    dim3 g(T_SEQ / 128, HDIM / 64, 3);
    proj_gemm<<<g, 256>>>(x, Uu, Ur, Uc, Bu, Br, Bc);

    scan_kernel<<<NBLK, 256>>>(Wu, Wr, Wc, out);
}